// round 9
// baseline (speedup 1.0000x reference)
#include <cuda_runtime.h>

#define BN_EPS 1e-5f

// ---------------- scratch (device globals; no allocations allowed) ----------------
__device__ float g_w2t[27 * 32 * 64];     // folded conv2 weights [(kk*32+ci)*64 + co]
__device__ float g_b2f[64];
__device__ float g_w3t[27 * 64 * 128];    // folded conv3 weights [(kk*64+ci)*128 + co]
__device__ float g_b3f[128];
__device__ float g_a1[16 * 343 * 32];     // conv1 cone activations [b][pos(7^3)][ci]
__device__ float g_a2[16 * 27 * 64];      // conv2 cone activations [b][pos(3^3)][co]
__device__ float g_p3[8 * 16 * 128];      // conv3 K-split partials [kc][b][co]
__device__ int   g_bar;                   // grid barrier counter (reset at kernel end)
__device__ int   g_fin;                   // tail-completion counter (reset at kernel end)

#define GRID_BLOCKS 148
#define CONV1_BLOCKS 112
#define PREP_BLOCKS  36

// Grid-wide barrier: safe because grid = 148 blocks = one wave (all co-resident).
__device__ __forceinline__ void gridbar(int target)
{
    __syncthreads();
    if (threadIdx.x == 0) {
        __threadfence();
        atomicAdd(&g_bar, 1);
        while (*(volatile int*)&g_bar < target) { }
        __threadfence();
    }
    __syncthreads();
}

__global__ __launch_bounds__(256)
void fused_kernel(const float* __restrict__ voxel,
    const float* __restrict__ w1, const float* __restrict__ g1, const float* __restrict__ b1,
    const float* __restrict__ m1, const float* __restrict__ v1,
    const float* __restrict__ w2, const float* __restrict__ g2, const float* __restrict__ b2,
    const float* __restrict__ m2, const float* __restrict__ v2,
    const float* __restrict__ w3, const float* __restrict__ g3, const float* __restrict__ b3,
    const float* __restrict__ m3, const float* __restrict__ v3,
    const float* __restrict__ wp, const float* __restrict__ bp,
    float* __restrict__ out)
{
    // shared scratch, aliased across phases (8.2KB total)
    __shared__ float4 s_buf4[216];     // conv1: s_in(243f) | conv2: patch | conv3: patch
    __shared__ float  s_red[1024];     // conv1: s_w(864f) | conv2/conv3: reduction
    __shared__ float  s_small[160];    // conv1: s_b(32f)  | tail: center(128f)

    int tid = threadIdx.x;
    int bid = blockIdx.x;

    // ================= phase 0: conv1 (blocks 0..111) + prep (112..147) =============
    if (bid < CONV1_BLOCKS) {
        float* s_in = (float*)s_buf4;
        float* s_w  = s_red;
        float* s_b  = s_small;

        int b  = bid / 7;
        int zi = bid % 7;   // output z' = 29+zi needs input z in [28+zi, 30+zi]

        for (int i = tid; i < 3 * 9 * 9; i += 256) {
            int lz = i / 81, r = i % 81, ly = r / 9, lx = r % 9;
            s_in[i] = voxel[(size_t)b * 262144 + (size_t)(28 + zi + lz) * 4096
                            + (28 + ly) * 64 + (28 + lx)];
        }
        for (int i = tid; i < 864; i += 256) {
            int c = i / 27;
            float s = g1[c] * rsqrtf(v1[c] + BN_EPS);
            s_w[i] = w1[i] * s;
        }
        if (tid < 32) {
            float s = g1[tid] * rsqrtf(v1[tid] + BN_EPS);
            s_b[tid] = b1[tid] - m1[tid] * s;
        }
        __syncthreads();

        if (tid < 196) {
            int pos = tid % 49;   // yi*7 + xi
            int cg  = tid / 49;   // channel group of 8
            int yi = pos / 7, xi = pos % 7;

            float x[27];
#pragma unroll
            for (int kz = 0; kz < 3; kz++)
#pragma unroll
                for (int ky = 0; ky < 3; ky++)
#pragma unroll
                    for (int kx = 0; kx < 3; kx++)
                        x[kz * 9 + ky * 3 + kx] = s_in[kz * 81 + (yi + ky) * 9 + (xi + kx)];

            int p3 = zi * 49 + pos;
#pragma unroll
            for (int cc = 0; cc < 8; cc++) {
                int c = cg * 8 + cc;
                float acc = s_b[c];
#pragma unroll
                for (int k = 0; k < 27; k++)
                    acc = fmaf(x[k], s_w[c * 27 + k], acc);
                g_a1[((size_t)b * 343 + p3) * 32 + c] = fmaxf(acc, 0.f);
            }
        }
    } else {
        // ---- prep: 36 blocks, exact trip counts (6 and 24) -> unrolled, high MLP ----
        int gid = (bid - CONV1_BLOCKS) * 256 + tid;   // 0..9215
        const int nth = PREP_BLOCKS * 256;            // 9216

        // w2t[(kk*32+ci)*64+co] = w2[(co*32+ci)*27+kk] * s2[co]   (55296 = 6*9216)
#pragma unroll
        for (int it = 0; it < 6; it++) {
            int j = gid + it * nth;
            int co = j / 864, r = j % 864, ci = r / 27, kk = r % 27;
            float s = g2[co] * rsqrtf(v2[co] + BN_EPS);
            g_w2t[(kk * 32 + ci) * 64 + co] = w2[j] * s;
        }
        // w3t[(kk*64+ci)*128+co] = w3[(co*64+ci)*27+kk] * s3[co]  (221184 = 24*9216)
#pragma unroll
        for (int it = 0; it < 24; it++) {
            int j = gid + it * nth;
            int co = j / 1728, r = j % 1728, ci = r / 27, kk = r % 27;
            float s = g3[co] * rsqrtf(v3[co] + BN_EPS);
            g_w3t[(kk * 64 + ci) * 128 + co] = w3[j] * s;
        }
        if (gid < 64) {
            float s = g2[gid] * rsqrtf(v2[gid] + BN_EPS);
            g_b2f[gid] = b2[gid] - m2[gid] * s;
        } else if (gid < 192) {
            int c = gid - 64;
            float s = g3[c] * rsqrtf(v3[c] + BN_EPS);
            g_b3f[c] = b3[c] - m3[c] * s;
        }
    }

    gridbar(GRID_BLOCKS);        // B1: g_a1, w2t/w3t, biases visible

    // ================= phase 1: conv2 — 432 units striped over 148 blocks ===========
    {
        float4* s_patch4 = s_buf4;
        const float4* w4 = (const float4*)g_w2t;     // [K][16 float4]

        for (int u = bid; u < 432; u += GRID_BLOCKS) {
            int b = u / 27, p = u % 27;
            int pz = p / 9, py = (p / 3) % 3, px = p % 3;

            if (tid < 216) {
                int kk = tid >> 3, lane = tid & 7;
                int kz = kk / 9, ky = (kk / 3) % 3, kx = kk % 3;
                int apos = (2 * pz + kz) * 49 + (2 * py + ky) * 7 + (2 * px + kx);
                s_patch4[tid] = __ldcg((const float4*)
                    (g_a1 + ((size_t)b * 343 + apos) * 32 + lane * 4));
            }
            __syncthreads();
            const float* s_patch = (const float*)s_patch4;

            int co4 = tid & 15;
            int ks  = tid >> 4;          // 16-way K split, 54 each
            int kb  = ks * 54;
            float4 acc = {0.f, 0.f, 0.f, 0.f};
#pragma unroll
            for (int k = 0; k < 54; k++) {
                float4 w = __ldcg(&w4[(kb + k) * 16 + co4]);
                float pv = s_patch[kb + k];
                acc.x = fmaf(pv, w.x, acc.x);
                acc.y = fmaf(pv, w.y, acc.y);
                acc.z = fmaf(pv, w.z, acc.z);
                acc.w = fmaf(pv, w.w, acc.w);
            }
            *(float4*)(s_red + ks * 64 + co4 * 4) = acc;
            __syncthreads();

            if (tid < 64) {
                float v = __ldcg(&g_b2f[tid]);
#pragma unroll
                for (int s = 0; s < 16; s++) v += s_red[s * 64 + tid];
                g_a2[((size_t)b * 27 + p) * 64 + tid] = fmaxf(v, 0.f);
            }
            __syncthreads();    // protect s_patch/s_red reuse in next unit
        }
    }

    gridbar(2 * GRID_BLOCKS);    // B2: g_a2 visible

    // ================= phase 2: conv3 partials (blocks 0..127) ======================
    if (bid < 128) {
        float4* s_patch4 = s_buf4;
        int b  = bid >> 3;
        int kc = bid & 7;

        if (tid < 54)
            s_patch4[tid] = __ldcg((const float4*)
                (g_a2 + (size_t)b * 1728 + kc * 216 + tid * 4));
        __syncthreads();
        const float* s_patch = (const float*)s_patch4;

        int co4 = tid & 31;
        int ks  = tid >> 5;          // 8-way sub-split, 27 K each
        int kb  = kc * 216 + ks * 27;
        int pb  = ks * 27;
        const float4* w4 = (const float4*)g_w3t;     // [K][32 float4]
        float4 acc = {0.f, 0.f, 0.f, 0.f};
#pragma unroll
        for (int k = 0; k < 27; k++) {
            float4 w = __ldcg(&w4[(kb + k) * 32 + co4]);
            float pv = s_patch[pb + k];
            acc.x = fmaf(pv, w.x, acc.x);
            acc.y = fmaf(pv, w.y, acc.y);
            acc.z = fmaf(pv, w.z, acc.z);
            acc.w = fmaf(pv, w.w, acc.w);
        }
        *(float4*)(s_red + ks * 128 + co4 * 4) = acc;
        __syncthreads();

        if (tid < 128) {
            float v = 0.f;
#pragma unroll
            for (int s = 0; s < 8; s++) v += s_red[s * 128 + tid];
            g_p3[kc * 2048 + b * 128 + tid] = v;
        }
    }

    // ---- B3 arrive (all 148 blocks); only tail blocks spin ----
    __syncthreads();
    if (tid == 0) {
        __threadfence();
        atomicAdd(&g_bar, 1);
    }

    if (bid < 16) {
        // ============= phase 3: tail — reduce + BN + ReLU + projection ==============
        if (tid == 0) {
            while (*(volatile int*)&g_bar < 3 * GRID_BLOCKS) { }
            __threadfence();
        }
        __syncthreads();

        int tb = bid;
        if (tid < 128) {
            float v = __ldcg(&g_b3f[tid]);
#pragma unroll
            for (int s = 0; s < 8; s++)
                v += __ldcg(&g_p3[s * 2048 + tb * 128 + tid]);
            s_small[tid] = fmaxf(v, 0.f);
        }
        __syncthreads();

        // projection: out[tb][f] = bp[f] + sum_c center[c] * wp[c*256+f]
        float o = bp[tid];
#pragma unroll 8
        for (int c = 0; c < 128; c++)
            o = fmaf(s_small[c], wp[c * 256 + tid], o);
        out[tb * 256 + tid] = o;

        // ---- counter reset protocol (replay determinism) ----
        __syncthreads();
        if (tid == 0) {
            atomicAdd(&g_fin, 1);
            if (bid == 0) {
                while (*(volatile int*)&g_fin < 16) { }
                g_bar = 0;      // no block reads g_bar/g_fin after this point
                g_fin = 0;
            }
        }
    }
}

// ---------------- launch -------------------------------------------------------------
extern "C" void kernel_launch(void* const* d_in, const int* in_sizes, int n_in,
                              void* d_out, int out_size)
{
    const float* voxel = (const float*)d_in[0];
    const float* w1 = (const float*)d_in[1];
    const float* g1 = (const float*)d_in[2];
    const float* b1 = (const float*)d_in[3];
    const float* m1 = (const float*)d_in[4];
    const float* v1 = (const float*)d_in[5];
    const float* w2 = (const float*)d_in[6];
    const float* g2 = (const float*)d_in[7];
    const float* b2 = (const float*)d_in[8];
    const float* m2 = (const float*)d_in[9];
    const float* v2 = (const float*)d_in[10];
    const float* w3 = (const float*)d_in[11];
    const float* g3 = (const float*)d_in[12];
    const float* b3 = (const float*)d_in[13];
    const float* m3 = (const float*)d_in[14];
    const float* v3 = (const float*)d_in[15];
    const float* wp = (const float*)d_in[16];
    const float* bp = (const float*)d_in[17];

    fused_kernel<<<GRID_BLOCKS, 256>>>(
        voxel, w1, g1, b1, m1, v1, w2, g2, b2, m2, v2, w3, g3, b3, m3, v3,
        wp, bp, (float*)d_out);
}